// round 7
// baseline (speedup 1.0000x reference)
#include <cuda_runtime.h>

// Problem constants
#define Bn      64
#define h_img   416
#define w_img   416
#define H_out   608
#define W_out   608
#define ROW_OFF 85
#define COL_OFF 80

#define W4      (W_out / 4)     // 152 float4 per output row
#define w4_     (w_img / 4)     // 104 float4 per img row
#define X4_OFF  (COL_OFF / 4)   // 20
#define PLANE   (H_out * W4)    // 92416 float4 per channel plane

// ---- Kernel A: frame region (pure broadcast ref -> out) -------------------
// Items per batch: 192 full rows * 152  +  416 strip rows * 48 = 49152 = 192*256
#define FULLROWS   192                 // rows y<85 plus y>=501
#define FULLPART   (FULLROWS * W4)     // 29184
#define STRIPC     48                  // 20 left + 28 right float4 per strip row
#define FRAME_PER_B 49152

__global__ void __launch_bounds__(256)
frame_kernel(const float4* __restrict__ ref, float4* __restrict__ out)
{
    const int idx = blockIdx.x * 256 + threadIdx.x;   // [0, FRAME_PER_B)
    const int b   = blockIdx.y;

    int y, x4;
    if (idx < FULLPART) {
        const int row = idx / W4;                     // 0..191
        y  = (row < ROW_OFF) ? row : row + h_img;     // skip pasted rows
        x4 = idx - (idx / W4) * W4;
    } else {
        const int t  = idx - FULLPART;                // strip region
        y  = ROW_OFF + t / STRIPC;
        const int c = t - (t / STRIPC) * STRIPC;
        x4 = (c < X4_OFF) ? c : c + w4_;              // left strip / right strip
    }

    const size_t r = (size_t)y * W4 + x4;
    const float4 o0 = ref[r];
    const float4 o1 = ref[r + (size_t)PLANE];
    const float4 o2 = ref[r + (size_t)2 * PLANE];

    const size_t o = (size_t)b * 3 * PLANE + r;
    __stcs(&out[o],                     o0);
    __stcs(&out[o + (size_t)PLANE],     o1);
    __stcs(&out[o + (size_t)2 * PLANE], o2);
}

// ---- Kernel B: paste window (compose img over ref) ------------------------
// Items per batch: 416 * 104 = 43264 = 169*256
#define WIN_PER_B  (h_img * w4_)

__global__ void __launch_bounds__(256)
window_kernel(const float4* __restrict__ img, const float4* __restrict__ ref,
              float4* __restrict__ out)
{
    const int idx = blockIdx.x * 256 + threadIdx.x;   // [0, WIN_PER_B)
    const int b   = blockIdx.y;

    const int ry  = idx / w4_;                        // 0..415
    const int rx4 = idx - ry * w4_;                   // 0..103
    const int y   = ry + ROW_OFF;
    const int x4  = rx4 + X4_OFF;

    // ref (L2-resident)
    const size_t r = (size_t)y * W4 + x4;
    float4 o0 = ref[r];
    float4 o1 = ref[r + (size_t)PLANE];
    float4 o2 = ref[r + (size_t)2 * PLANE];

    // img (streamed, read-once). channel 2 = mask and payload.
    const size_t ib = (size_t)b * 3 * h_img * w4_ + (size_t)ry * w4_ + rx4;
    const float4 m  = __ldcs(&img[ib + (size_t)2 * h_img * w4_]);
    const float4 i0 = __ldcs(&img[ib]);
    const float4 i1 = __ldcs(&img[ib + (size_t)1 * h_img * w4_]);

    if (m.x != 0.0f) { o0.x = i0.x; o1.x = i1.x; o2.x = m.x; }
    if (m.y != 0.0f) { o0.y = i0.y; o1.y = i1.y; o2.y = m.y; }
    if (m.z != 0.0f) { o0.z = i0.z; o1.z = i1.z; o2.z = m.z; }
    if (m.w != 0.0f) { o0.w = i0.w; o1.w = i1.w; o2.w = m.w; }

    const size_t o = (size_t)b * 3 * PLANE + r;
    __stcs(&out[o],                     o0);
    __stcs(&out[o + (size_t)PLANE],     o1);
    __stcs(&out[o + (size_t)2 * PLANE], o2);
}

extern "C" void kernel_launch(void* const* d_in, const int* in_sizes, int n_in,
                              void* d_out, int out_size)
{
    const float4* img = (const float4*)d_in[0];   // [64,3,416,416] f32
    const float4* ref = (const float4*)d_in[1];   // [1,3,608,608]  f32
    float4* out = (float4*)d_out;                 // [64,3,608,608] f32

    dim3 gA(FRAME_PER_B / 256, Bn);   // (192, 64) — pure-write broadcast
    dim3 gB(WIN_PER_B  / 256, Bn);    // (169, 64) — balanced R/W composite
    frame_kernel<<<gA, 256>>>(ref, out);
    window_kernel<<<gB, 256>>>(img, ref, out);
}

// round 10
// speedup vs baseline: 1.0312x; 1.0312x over previous
#include <cuda_runtime.h>

// Problem constants (from reference_code)
#define Bn      64
#define h_img   416
#define w_img   416
#define H_out   608
#define W_out   608
#define ROW_OFF 85
#define COL_OFF 80

#define W4     (W_out / 4)    // 152 float4 per output row
#define w4_    (w_img / 4)    // 104 float4 per img row
#define X4_OFF (COL_OFF / 4)  // 20  (aligned: COL_OFF % 4 == 0)

// W4 * H_out = 152 * 608 = 92416 = 361 * 256  -> exact grid, no bounds check

__global__ void __launch_bounds__(256, 8)
composite_kernel(const float4* __restrict__ img,   // [B,3,h,w] as float4
                 const float4* __restrict__ ref,   // [1,3,H,W] as float4
                 float4* __restrict__ out)         // [B,3,H,W] as float4
{
    const int idx = blockIdx.x * 256 + threadIdx.x;   // 0 .. 92415, covers (y, x4)
    const int b   = blockIdx.y;

    const int x4 = idx % W4;
    const int y  = idx / W4;

    // Reference pixels, all 3 channels (4.4 MB tensor -> L2-resident)
    float4 o0 = ref[(size_t)(0 * H_out + y) * W4 + x4];
    float4 o1 = ref[(size_t)(1 * H_out + y) * W4 + x4];
    float4 o2 = ref[(size_t)(2 * H_out + y) * W4 + x4];

    const int ry  = y  - ROW_OFF;
    const int rx4 = x4 - X4_OFF;
    if (ry >= 0 && ry < h_img && rx4 >= 0 && rx4 < w4_) {
        const size_t ibase = (size_t)b * 3 * h_img * w4_ + (size_t)ry * w4_ + rx4;
        // channel 2 is both mask and payload; stream (read-once)
        const float4 m  = __ldcs(&img[ibase + (size_t)2 * h_img * w4_]);
        const float4 i0 = __ldcs(&img[ibase]);
        const float4 i1 = __ldcs(&img[ibase + (size_t)1 * h_img * w4_]);

        if (m.x != 0.0f) { o0.x = i0.x; o1.x = i1.x; o2.x = m.x; }
        if (m.y != 0.0f) { o0.y = i0.y; o1.y = i1.y; o2.y = m.y; }
        if (m.z != 0.0f) { o0.z = i0.z; o1.z = i1.z; o2.z = m.z; }
        if (m.w != 0.0f) { o0.w = i0.w; o1.w = i1.w; o2.w = m.w; }
    }

    // Default (evict-normal) stores: let L2 buffer dirty lines and batch
    // DRAM writebacks, instead of __stcs evict-first streaming.
    const size_t obase = (size_t)b * 3 * H_out * W4 + (size_t)y * W4 + x4;
    out[obase]                          = o0;
    out[obase + (size_t)1 * H_out * W4] = o1;
    out[obase + (size_t)2 * H_out * W4] = o2;
}

extern "C" void kernel_launch(void* const* d_in, const int* in_sizes, int n_in,
                              void* d_out, int out_size)
{
    const float4* img = (const float4*)d_in[0];   // [64,3,416,416] f32
    const float4* ref = (const float4*)d_in[1];   // [1,3,608,608]  f32
    float4* out = (float4*)d_out;                 // [64,3,608,608] f32

    dim3 grid(361, Bn);   // 361*256 == 152*608 exactly; y-dim = batch
    composite_kernel<<<grid, 256>>>(img, ref, out);
}

// round 11
// speedup vs baseline: 1.0388x; 1.0074x over previous
#include <cuda_runtime.h>

// Problem constants (from reference_code)
#define Bn      64
#define Cn      3
#define h_img   416
#define w_img   416
#define H_out   608
#define W_out   608
#define ROW_OFF 85
#define COL_OFF 80

#define W4   (W_out / 4)   // 152 float4 per output row
#define w4   (w_img / 4)   // 104 float4 per img row
#define X4_OFF (COL_OFF / 4) // 20  (COL_OFF divisible by 4 -> aligned)

__global__ void __launch_bounds__(256)
composite_kernel(const float4* __restrict__ img,   // [B,3,h,w] as float4
                 const float4* __restrict__ ref,   // [1,3,H,W] as float4
                 float4* __restrict__ out)         // [B,3,H,W] as float4
{
    const int total = Bn * H_out * W4;
    int idx = blockIdx.x * blockDim.x + threadIdx.x;
    if (idx >= total) return;

    int x4 = idx % W4;
    int t  = idx / W4;
    int y  = t % H_out;
    int b  = t / H_out;

    // Reference pixels for all 3 channels (small tensor, L2-resident; default cache)
    const float4 r0 = ref[(size_t)(0 * H_out + y) * W4 + x4];
    const float4 r1 = ref[(size_t)(1 * H_out + y) * W4 + x4];
    const float4 r2 = ref[(size_t)(2 * H_out + y) * W4 + x4];

    float4 o0 = r0, o1 = r1, o2 = r2;

    const int ry  = y  - ROW_OFF;
    const int rx4 = x4 - X4_OFF;
    if (ry >= 0 && ry < h_img && rx4 >= 0 && rx4 < w4) {
        const size_t ibase = (size_t)b * 3 * h_img * w4;
        // Channel 2 is both the mask and the channel-2 payload.
        const float4 m  = __ldcs(&img[ibase + (size_t)(2 * h_img + ry) * w4 + rx4]);
        const float4 i0 = __ldcs(&img[ibase + (size_t)(0 * h_img + ry) * w4 + rx4]);
        const float4 i1 = __ldcs(&img[ibase + (size_t)(1 * h_img + ry) * w4 + rx4]);

        if (m.x != 0.0f) { o0.x = i0.x; o1.x = i1.x; o2.x = m.x; }
        if (m.y != 0.0f) { o0.y = i0.y; o1.y = i1.y; o2.y = m.y; }
        if (m.z != 0.0f) { o0.z = i0.z; o1.z = i1.z; o2.z = m.z; }
        if (m.w != 0.0f) { o0.w = i0.w; o1.w = i1.w; o2.w = m.w; }
    }

    const size_t obase = (size_t)b * 3 * H_out * W4;
    __stcs(&out[obase + (size_t)(0 * H_out + y) * W4 + x4], o0);
    __stcs(&out[obase + (size_t)(1 * H_out + y) * W4 + x4], o1);
    __stcs(&out[obase + (size_t)(2 * H_out + y) * W4 + x4], o2);
}

extern "C" void kernel_launch(void* const* d_in, const int* in_sizes, int n_in,
                              void* d_out, int out_size)
{
    const float4* img = (const float4*)d_in[0];   // [64,3,416,416] f32
    const float4* ref = (const float4*)d_in[1];   // [1,3,608,608]  f32
    float4* out = (float4*)d_out;                 // [64,3,608,608] f32

    const int total = Bn * H_out * W4;            // 5,910,528 threads
    const int threads = 256;
    const int blocks = (total + threads - 1) / threads;
    composite_kernel<<<blocks, threads>>>(img, ref, out);
}